// round 14
// baseline (speedup 1.0000x reference)
#include <cuda_runtime.h>
#include <cuda_bf16.h>
#include <cstdint>

// ContrastiveLoss: N=8192, D=256, 64 classes, T=0.5.
// loss = [ sum_i P_i*(2 + log(denom_i)) - possum_total ] / n_pos
//   denom_i = sum_{j!=i} exp(sim_ij - 2)   (shift-invariant; sim<=2)
//   possum_total = 2*sum_c |C_c|^2 - 2N,  C_c = sum_{lab=c} E_i  (unit-norm E)
// R12: R11 champion + (a) self-term included in GEMM epilogue and subtracted
// as exp(0)=1 in the reduce (branch-free uniform epilogue; unit-norm rows),
// (b) final_kernel folded into reduce via last-block counter.

#define N_ROWS 8192
#define DIM    256                     // fp8 elements per row (= 256 bytes)
#define DIMH   128                     // b16 (fp8-pair) units per row
#define NCLS   64
#define BM     128
#define BN     128
#define SSTRIDE 136                    // b16 units per smem row (128 + 8 pad)
#define SROWB  (SSTRIDE * 2)           // 272 bytes per smem row
#define NB     (N_ROWS / BM)           // 64
#define NTILES (NB * (NB + 1) / 2)     // 2080 upper-tri tiles
#define NTHR   256
#define RBLKS  (N_ROWS / 256)          // 32 reduce blocks

__device__ float   g_denom[N_ROWS];
__device__ float   g_C[NCLS * DIM];    // fp32 class-sum vectors
__device__ uint8_t g_E8[N_ROWS * DIM];
__device__ int     g_cnt[NCLS];
__device__ double  g_acc;
__device__ int     g_rdone;            // reduce completion counter (prep-reset)
__device__ int     g_is64;

__device__ __forceinline__ uint32_t smem_u32(const void* p) {
    uint32_t a;
    asm("{ .reg .u64 t; cvta.to.shared.u64 t, %1; cvt.u32.u64 %0, t; }" : "=r"(a) : "l"(p));
    return a;
}
__device__ __forceinline__ void ldsm_x4(uint32_t& r0, uint32_t& r1, uint32_t& r2, uint32_t& r3,
                                        uint32_t addr) {
    asm volatile("ldmatrix.sync.aligned.m8n8.x4.shared.b16 {%0,%1,%2,%3}, [%4];"
                 : "=r"(r0), "=r"(r1), "=r"(r2), "=r"(r3) : "r"(addr));
}
__device__ __forceinline__ void mma_fp8(float* d, const uint32_t* a, uint32_t b0, uint32_t b1) {
    asm volatile(
        "mma.sync.aligned.m16n8k32.row.col.f32.e4m3.e4m3.f32 "
        "{%0,%1,%2,%3}, {%4,%5,%6,%7}, {%8,%9}, {%0,%1,%2,%3};"
        : "+f"(d[0]), "+f"(d[1]), "+f"(d[2]), "+f"(d[3])
        : "r"(a[0]), "r"(a[1]), "r"(a[2]), "r"(a[3]), "r"(b0), "r"(b1));
}
__device__ __forceinline__ float ex2f(float x) {
    float y;
    asm("ex2.approx.f32 %0, %1;" : "=f"(y) : "f"(x));
    return y;
}
__device__ __forceinline__ float lg2f(float x) {
    float y;
    asm("lg2.approx.f32 %0, %1;" : "=f"(y) : "f"(x));
    return y;
}
#define CP_ASYNC16(sm, gp) asm volatile("cp.async.cg.shared.global [%0], [%1], 16;" :: "r"(sm), "l"(gp) : "memory")
#define CP_COMMIT()        asm volatile("cp.async.commit_group;" ::: "memory")
#define CP_WAIT0()         asm volatile("cp.async.wait_group 0;" ::: "memory")

// ---- label width detection: int64 labels (<64) have zero high words ----
__device__ __forceinline__ int detect_is64(const int* L) {
    int s = 0;
#pragma unroll
    for (int k = 0; k < 64; k++) s |= L[2 * k + 1];
    return (s == 0) ? 1 : 0;
}
__device__ __forceinline__ int get_label(const int* L, int i, int is64) {
    return is64 ? L[2 * i] : L[i];
}

// ---- prep: detect label width, zero accumulators, convert E to fp8 ----
__global__ void prep_kernel(const float* __restrict__ E, const int* __restrict__ Lraw) {
    int i = blockIdx.x * blockDim.x + threadIdx.x;   // one float4 -> 4 fp8
    if (i == 0) { g_is64 = detect_is64(Lraw); g_acc = 0.0; g_rdone = 0; }
    if (i < N_ROWS) g_denom[i] = 0.f;
    float4 v = ((const float4*)E)[i];
    uint16_t h0, h1;
    asm("cvt.rn.satfinite.e4m3x2.f32 %0, %1, %2;" : "=h"(h0) : "f"(v.y), "f"(v.x));
    asm("cvt.rn.satfinite.e4m3x2.f32 %0, %1, %2;" : "=h"(h1) : "f"(v.w), "f"(v.z));
    ((uint32_t*)g_E8)[i] = (uint32_t)h0 | ((uint32_t)h1 << 16);
}

// ---- class sums C_c (fp32): block b owns dims [4b, 4b+4); block 0 also
// builds the label histogram (smem atomics, plain store to g_cnt). ----
__global__ void csum_kernel(const float* __restrict__ E, const int* __restrict__ Lraw) {
    __shared__ float sC[NCLS][4];
    __shared__ int   scnt[NCLS];
    const int tid = threadIdx.x;
    const int dbase = blockIdx.x * 4;
    sC[tid >> 2][tid & 3] = 0.f;                    // 256 = NCLS*4
    if (tid < NCLS) scnt[tid] = 0;
    __syncthreads();
    const int is64 = g_is64;
    const bool dohist = (blockIdx.x == 0);
    for (int i = tid; i < N_ROWS; i += 256) {
        const int lab = get_label(Lraw, i, is64);
        if (dohist) atomicAdd(&scnt[lab], 1);
        float4 v = *(const float4*)(E + (size_t)i * DIM + dbase);
        atomicAdd(&sC[lab][0], v.x);
        atomicAdd(&sC[lab][1], v.y);
        atomicAdd(&sC[lab][2], v.z);
        atomicAdd(&sC[lab][3], v.w);
    }
    __syncthreads();
    g_C[(tid >> 2) * DIM + dbase + (tid & 3)] = sC[tid >> 2][tid & 3];
    if (dohist && tid < NCLS) g_cnt[tid] = scnt[tid];
}

// ---- fused FP8 GEMM + branch-free denom epilogue; upper-tri tiles ----
// 256 threads = 8 warps in 2(m) x 4(n); warp tile 64x32; full K resident.
// Self-similarity terms are INCLUDED here (exp(2|q(e)|^2-2) ~ 1) and
// compensated by log(denom - 1) in the reduce.
__global__ __launch_bounds__(NTHR, 2)
void sim_kernel() {
    extern __shared__ __align__(16) char smem[];   // A[128][272B] | B[128][272B]
    __shared__ float redD[BM], redDc[BN];

    const int tid  = threadIdx.x;
    const int wid  = tid >> 5, lane = tid & 31;
    const int wm   = wid >> 2, wn = wid & 3;          // 2x4 warp grid

    // ---- linear tile id -> upper-triangular (bi, bj) ----
    const int t = blockIdx.x;
    int bi = (int)((2.0f * NB + 1.0f -
                    sqrtf((2.0f * NB + 1.0f) * (2.0f * NB + 1.0f) - 8.0f * (float)t)) * 0.5f);
    while (bi > 0 && bi * NB - bi * (bi - 1) / 2 > t) bi--;
    while ((bi + 1) * NB - (bi + 1) * bi / 2 <= t) bi++;
    const int bj = bi + (t - (bi * NB - bi * (bi - 1) / 2));
    const int row0 = bi * BM, col0 = bj * BN;
    const bool offdiag = (bi != bj);

    const uint32_t sbase = smem_u32(smem);
    const uint32_t stB = sbase + (uint32_t)(BM * SROWB);

    if (tid < BM) { redD[tid] = 0.f; redDc[tid] = 0.f; }

    // ---- one-shot async load: A and B tiles, 128 x 256B each ----
    {
        const uint8_t* gA = g_E8 + (size_t)row0 * DIM;
        const uint8_t* gB = g_E8 + (size_t)col0 * DIM;
#pragma unroll
        for (int u = 0; u < 8; u++) {
            int idx = tid + u * NTHR;                  // 0..2047 16B units
            int r = idx >> 4, c16 = idx & 15;
            uint32_t so = (uint32_t)(r * SROWB + c16 * 16);
            const size_t go = (size_t)r * DIM + c16 * 16;
            CP_ASYNC16(sbase + so, gA + go);
            CP_ASYNC16(stB + so, gB + go);
        }
        CP_COMMIT();
    }

    float acc[4][4][4];
#pragma unroll
    for (int mf = 0; mf < 4; mf++)
#pragma unroll
        for (int nf = 0; nf < 4; nf++)
#pragma unroll
            for (int e = 0; e < 4; e++) acc[mf][nf][e] = 0.f;

    // fragment address components (b16-unit coords; x2 for bytes)
    const uint32_t aRow = (uint32_t)(wm * 64 + (lane & 15));
    const uint32_t aKof = (uint32_t)((lane >> 4) * 8);
    const uint32_t bRow = (uint32_t)(wn * 32 + (lane & 7) + ((lane >> 4) << 3));
    const uint32_t bKof = (uint32_t)(((lane >> 3) & 1) * 8);

    CP_WAIT0();
    __syncthreads();

    // ---- mainloop: 8 k-steps of k32 fp8, full K resident, no syncs ----
#pragma unroll
    for (int ks = 0; ks < DIMH / 16; ks++) {
        const uint32_t k0 = ks * 16;
        uint32_t a[4][4], b[2][4];
#pragma unroll
        for (int nb = 0; nb < 2; nb++)
            ldsm_x4(b[nb][0], b[nb][1], b[nb][2], b[nb][3],
                    stB + ((bRow + nb * 16) * SSTRIDE + k0 + bKof) * 2u);
#pragma unroll
        for (int mf = 0; mf < 4; mf++)
            ldsm_x4(a[mf][0], a[mf][1], a[mf][2], a[mf][3],
                    sbase + ((aRow + mf * 16) * SSTRIDE + k0 + aKof) * 2u);
#pragma unroll
        for (int mf = 0; mf < 4; mf++)
#pragma unroll
            for (int nf = 0; nf < 4; nf++)
                mma_fp8(acc[mf][nf], a[mf], b[nf >> 1][(nf & 1) * 2],
                        b[nf >> 1][(nf & 1) * 2 + 1]);
    }

    // ---- branch-free epilogue: exp(2*acc - 2) = 2^(K1*acc + K0) ----
    const int rbase = wm * 64 + (lane >> 2);
    const float K1 = 2.8853900817779268f;              // 2*log2(e)
    const float K0 = -2.8853900817779268f;

    float dR[8];
#pragma unroll
    for (int x = 0; x < 8; x++) dR[x] = 0.f;

#pragma unroll
    for (int nf = 0; nf < 4; nf++) {
#pragma unroll
        for (int e = 0; e < 2; e++) {
            const int cloc = wn * 32 + nf * 8 + 2 * (lane & 3) + e;
            float dc = 0.f;
#pragma unroll
            for (int mf = 0; mf < 4; mf++) {
#pragma unroll
                for (int h = 0; h < 2; h++) {
                    const float ex = ex2f(fmaf(acc[mf][nf][h * 2 + e], K1, K0));
                    dR[mf * 2 + h] += ex;
                    dc += ex;
                }
            }
            if (offdiag) {                             // col sums only off-diag
                dc += __shfl_xor_sync(0xFFFFFFFF, dc, 4);
                dc += __shfl_xor_sync(0xFFFFFFFF, dc, 8);
                dc += __shfl_xor_sync(0xFFFFFFFF, dc, 16);
                if ((lane >> 2) == 0) atomicAdd(&redDc[cloc], dc);
            }
        }
    }
#pragma unroll
    for (int x = 0; x < 8; x++) {
        float d = dR[x];
        d += __shfl_xor_sync(0xFFFFFFFF, d, 1);
        d += __shfl_xor_sync(0xFFFFFFFF, d, 2);
        if ((lane & 3) == 0) {
            const int rloc = rbase + (x >> 1) * 16 + 8 * (x & 1);
            atomicAdd(&redD[rloc], d);
        }
    }

    __syncthreads();
    if (tid < BM) {
        atomicAdd(&g_denom[row0 + tid], redD[tid]);
        if (offdiag) atomicAdd(&g_denom[col0 + tid], redDc[tid]);
    }
}

// ---- parallel reduce + fused final (last block writes the scalar) ----
__global__ void reduce_kernel(const int* __restrict__ Lraw, float* __restrict__ out) {
    __shared__ double red[256];
    __shared__ int s_last;
    const int tid = threadIdx.x;
    const int i = blockIdx.x * 256 + tid;              // row id, 0..8191
    const int is64 = g_is64;
    const float LN2 = 0.6931471805599453f;

    const int P = g_cnt[get_label(Lraw, i, is64)] - 1;
    // self term (~exp(0)=1) was included in the GEMM epilogue; remove it here
    const float lg = lg2f(g_denom[i] - 1.0f) * LN2;    // log(denom)
    double v = (double)P * (2.0 + (double)lg);

    const float c0 = g_C[2 * i];                       // 16384 C elems, 2/thread
    const float c1 = g_C[2 * i + 1];
    v -= 2.0 * ((double)c0 * c0 + (double)c1 * c1);

    red[tid] = v;
    __syncthreads();
    for (int s = 128; s > 0; s >>= 1) {
        if (tid < s) red[tid] += red[tid + s];
        __syncthreads();
    }
    if (tid == 0) {
        atomicAdd(&g_acc, red[0]);
        __threadfence();
        s_last = (atomicAdd(&g_rdone, 1) == RBLKS - 1) ? 1 : 0;
    }
    __syncthreads();
    if (s_last && tid == 0) {
        __threadfence();
        long long npos = 0;
#pragma unroll
        for (int c = 0; c < NCLS; c++) {
            long long k = g_cnt[c];
            npos += k * (k - 1);
        }
        out[0] = (float)((g_acc + 2.0 * (double)N_ROWS) / (double)npos);
    }
}

extern "C" void kernel_launch(void* const* d_in, const int* in_sizes, int n_in,
                              void* d_out, int out_size) {
    const float* E    = (const float*)d_in[0];
    const int*   Lraw = (const int*)d_in[1];   // width auto-detected on device
    float* out = (float*)d_out;

    const int DYN_SMEM = 2 * BM * SROWB;       // A+B tiles, full K: 69632 B
    cudaFuncSetAttribute(sim_kernel, cudaFuncAttributeMaxDynamicSharedMemorySize, DYN_SMEM);

    prep_kernel<<<(N_ROWS * DIM / 4) / 256, 256>>>(E, Lraw);
    csum_kernel<<<DIM / 4, 256>>>(E, Lraw);
    sim_kernel<<<NTILES, NTHR, DYN_SMEM>>>();
    reduce_kernel<<<RBLKS, 256>>>(Lraw, out);
}

// round 15
// speedup vs baseline: 1.0228x; 1.0228x over previous
#include <cuda_runtime.h>
#include <cuda_bf16.h>
#include <cstdint>

// ContrastiveLoss: N=8192, D=256, 64 classes, T=0.5.
// loss = [ sum_i P_i*(2 + log denom_i) - possum_total ] / n_pos
//   denom_i = sum_{j!=i} exp(sim_ij - 2)       (shift-invariant; sim<=2)
//   possum_total = 2*sum_c |C_c|^2 - 2N,  C_c = sum_{lab=c} E_i  (unit-norm E)
// R14 = R11 champion (FP8 GEMM + denom-only epilogue + parallel finalize)
// with prep MLP=4 (was latency-bound at MLP=1) and shfl-based reduce.

#define N_ROWS 8192
#define DIM    256                     // fp8 elements per row (= 256 bytes)
#define DIMH   128                     // b16 (fp8-pair) units per row
#define NCLS   64
#define BM     128
#define BN     128
#define SSTRIDE 136                    // b16 units per smem row (128 + 8 pad)
#define SROWB  (SSTRIDE * 2)           // 272 bytes per smem row
#define NB     (N_ROWS / BM)           // 64
#define NTILES (NB * (NB + 1) / 2)     // 2080 upper-tri tiles
#define NTHR   256

__device__ float   g_denom[N_ROWS];
__device__ float   g_C[NCLS * DIM];    // fp32 class-sum vectors
__device__ uint8_t g_E8[N_ROWS * DIM];
__device__ int     g_cnt[NCLS];
__device__ double  g_acc;
__device__ int     g_is64;

__device__ __forceinline__ uint32_t smem_u32(const void* p) {
    uint32_t a;
    asm("{ .reg .u64 t; cvta.to.shared.u64 t, %1; cvt.u32.u64 %0, t; }" : "=r"(a) : "l"(p));
    return a;
}
__device__ __forceinline__ void ldsm_x4(uint32_t& r0, uint32_t& r1, uint32_t& r2, uint32_t& r3,
                                        uint32_t addr) {
    asm volatile("ldmatrix.sync.aligned.m8n8.x4.shared.b16 {%0,%1,%2,%3}, [%4];"
                 : "=r"(r0), "=r"(r1), "=r"(r2), "=r"(r3) : "r"(addr));
}
__device__ __forceinline__ void mma_fp8(float* d, const uint32_t* a, uint32_t b0, uint32_t b1) {
    asm volatile(
        "mma.sync.aligned.m16n8k32.row.col.f32.e4m3.e4m3.f32 "
        "{%0,%1,%2,%3}, {%4,%5,%6,%7}, {%8,%9}, {%0,%1,%2,%3};"
        : "+f"(d[0]), "+f"(d[1]), "+f"(d[2]), "+f"(d[3])
        : "r"(a[0]), "r"(a[1]), "r"(a[2]), "r"(a[3]), "r"(b0), "r"(b1));
}
__device__ __forceinline__ float ex2f(float x) {
    float y;
    asm("ex2.approx.f32 %0, %1;" : "=f"(y) : "f"(x));
    return y;
}
__device__ __forceinline__ float lg2f(float x) {
    float y;
    asm("lg2.approx.f32 %0, %1;" : "=f"(y) : "f"(x));
    return y;
}
#define CP_ASYNC16(sm, gp) asm volatile("cp.async.cg.shared.global [%0], [%1], 16;" :: "r"(sm), "l"(gp) : "memory")
#define CP_COMMIT()        asm volatile("cp.async.commit_group;" ::: "memory")
#define CP_WAIT0()         asm volatile("cp.async.wait_group 0;" ::: "memory")

// ---- label width detection: int64 labels (<64) have zero high words ----
__device__ __forceinline__ int detect_is64(const int* L) {
    int s = 0;
#pragma unroll
    for (int k = 0; k < 64; k++) s |= L[2 * k + 1];
    return (s == 0) ? 1 : 0;
}
__device__ __forceinline__ int get_label(const int* L, int i, int is64) {
    return is64 ? L[2 * i] : L[i];
}

// ---- prep: MLP=4 convert (4 independent float4 -> 16 fp8 per thread) ----
__global__ void prep_kernel(const float* __restrict__ E, const int* __restrict__ Lraw) {
    const int j = blockIdx.x * blockDim.x + threadIdx.x;   // 131072 threads
    if (j == 0) { g_is64 = detect_is64(Lraw); g_acc = 0.0; }
    if (j < N_ROWS) g_denom[j] = 0.f;

    float4 v0 = ((const float4*)E)[4 * j + 0];
    float4 v1 = ((const float4*)E)[4 * j + 1];
    float4 v2 = ((const float4*)E)[4 * j + 2];
    float4 v3 = ((const float4*)E)[4 * j + 3];
    uint16_t a0, a1, b0, b1, c0, c1, d0, d1;
    asm("cvt.rn.satfinite.e4m3x2.f32 %0, %1, %2;" : "=h"(a0) : "f"(v0.y), "f"(v0.x));
    asm("cvt.rn.satfinite.e4m3x2.f32 %0, %1, %2;" : "=h"(a1) : "f"(v0.w), "f"(v0.z));
    asm("cvt.rn.satfinite.e4m3x2.f32 %0, %1, %2;" : "=h"(b0) : "f"(v1.y), "f"(v1.x));
    asm("cvt.rn.satfinite.e4m3x2.f32 %0, %1, %2;" : "=h"(b1) : "f"(v1.w), "f"(v1.z));
    asm("cvt.rn.satfinite.e4m3x2.f32 %0, %1, %2;" : "=h"(c0) : "f"(v2.y), "f"(v2.x));
    asm("cvt.rn.satfinite.e4m3x2.f32 %0, %1, %2;" : "=h"(c1) : "f"(v2.w), "f"(v2.z));
    asm("cvt.rn.satfinite.e4m3x2.f32 %0, %1, %2;" : "=h"(d0) : "f"(v3.y), "f"(v3.x));
    asm("cvt.rn.satfinite.e4m3x2.f32 %0, %1, %2;" : "=h"(d1) : "f"(v3.w), "f"(v3.z));
    uint4 o;
    o.x = (uint32_t)a0 | ((uint32_t)a1 << 16);
    o.y = (uint32_t)b0 | ((uint32_t)b1 << 16);
    o.z = (uint32_t)c0 | ((uint32_t)c1 << 16);
    o.w = (uint32_t)d0 | ((uint32_t)d1 << 16);
    ((uint4*)g_E8)[j] = o;
}

// ---- class sums C_c (fp32): block b owns dims [4b, 4b+4); block 0 also
// builds the label histogram (smem atomics, plain store to g_cnt). ----
__global__ void csum_kernel(const float* __restrict__ E, const int* __restrict__ Lraw) {
    __shared__ float sC[NCLS][4];
    __shared__ int   scnt[NCLS];
    const int tid = threadIdx.x;
    const int dbase = blockIdx.x * 4;
    sC[tid >> 2][tid & 3] = 0.f;                    // 256 = NCLS*4
    if (tid < NCLS) scnt[tid] = 0;
    __syncthreads();
    const int is64 = g_is64;
    const bool dohist = (blockIdx.x == 0);
    for (int i = tid; i < N_ROWS; i += 256) {
        const int lab = get_label(Lraw, i, is64);
        if (dohist) atomicAdd(&scnt[lab], 1);
        float4 v = *(const float4*)(E + (size_t)i * DIM + dbase);
        atomicAdd(&sC[lab][0], v.x);
        atomicAdd(&sC[lab][1], v.y);
        atomicAdd(&sC[lab][2], v.z);
        atomicAdd(&sC[lab][3], v.w);
    }
    __syncthreads();
    g_C[(tid >> 2) * DIM + dbase + (tid & 3)] = sC[tid >> 2][tid & 3];
    if (dohist && tid < NCLS) g_cnt[tid] = scnt[tid];
}

// ---- fused FP8 GEMM + denom-only dual epilogue; upper-tri tiles ----
// 256 threads = 8 warps in 2(m) x 4(n); warp tile 64x32; full K resident.
__global__ __launch_bounds__(NTHR, 2)
void sim_kernel() {
    extern __shared__ __align__(16) char smem[];   // A[128][272B] | B[128][272B]
    __shared__ float redD[BM], redDc[BN];

    const int tid  = threadIdx.x;
    const int wid  = tid >> 5, lane = tid & 31;
    const int wm   = wid >> 2, wn = wid & 3;          // 2x4 warp grid

    // ---- linear tile id -> upper-triangular (bi, bj) ----
    const int t = blockIdx.x;
    int bi = (int)((2.0f * NB + 1.0f -
                    sqrtf((2.0f * NB + 1.0f) * (2.0f * NB + 1.0f) - 8.0f * (float)t)) * 0.5f);
    while (bi > 0 && bi * NB - bi * (bi - 1) / 2 > t) bi--;
    while ((bi + 1) * NB - (bi + 1) * bi / 2 <= t) bi++;
    const int bj = bi + (t - (bi * NB - bi * (bi - 1) / 2));
    const int row0 = bi * BM, col0 = bj * BN;
    const bool offdiag = (bi != bj);

    const uint32_t sbase = smem_u32(smem);
    const uint32_t stB = sbase + (uint32_t)(BM * SROWB);

    if (tid < BM) { redD[tid] = 0.f; redDc[tid] = 0.f; }

    // ---- one-shot async load: A and B tiles, 128 x 256B each ----
    {
        const uint8_t* gA = g_E8 + (size_t)row0 * DIM;
        const uint8_t* gB = g_E8 + (size_t)col0 * DIM;
#pragma unroll
        for (int u = 0; u < 8; u++) {
            int idx = tid + u * NTHR;                  // 0..2047 16B units
            int r = idx >> 4, c16 = idx & 15;
            uint32_t so = (uint32_t)(r * SROWB + c16 * 16);
            const size_t go = (size_t)r * DIM + c16 * 16;
            CP_ASYNC16(sbase + so, gA + go);
            CP_ASYNC16(stB + so, gB + go);
        }
        CP_COMMIT();
    }

    float acc[4][4][4];
#pragma unroll
    for (int mf = 0; mf < 4; mf++)
#pragma unroll
        for (int nf = 0; nf < 4; nf++)
#pragma unroll
            for (int e = 0; e < 4; e++) acc[mf][nf][e] = 0.f;

    // fragment address components (b16-unit coords; x2 for bytes)
    const uint32_t aRow = (uint32_t)(wm * 64 + (lane & 15));
    const uint32_t aKof = (uint32_t)((lane >> 4) * 8);
    const uint32_t bRow = (uint32_t)(wn * 32 + (lane & 7) + ((lane >> 4) << 3));
    const uint32_t bKof = (uint32_t)(((lane >> 3) & 1) * 8);

    CP_WAIT0();
    __syncthreads();

    // ---- mainloop: 8 k-steps of k32 fp8, full K resident, no syncs ----
#pragma unroll
    for (int ks = 0; ks < DIMH / 16; ks++) {
        const uint32_t k0 = ks * 16;
        uint32_t a[4][4], b[2][4];
#pragma unroll
        for (int nb = 0; nb < 2; nb++)
            ldsm_x4(b[nb][0], b[nb][1], b[nb][2], b[nb][3],
                    stB + ((bRow + nb * 16) * SSTRIDE + k0 + bKof) * 2u);
#pragma unroll
        for (int mf = 0; mf < 4; mf++)
            ldsm_x4(a[mf][0], a[mf][1], a[mf][2], a[mf][3],
                    sbase + ((aRow + mf * 16) * SSTRIDE + k0 + aKof) * 2u);
#pragma unroll
        for (int mf = 0; mf < 4; mf++)
#pragma unroll
            for (int nf = 0; nf < 4; nf++)
                mma_fp8(acc[mf][nf], a[mf], b[nf >> 1][(nf & 1) * 2],
                        b[nf >> 1][(nf & 1) * 2 + 1]);
    }

    // ---- denom-only epilogue: exp(2*acc - 2) = 2^(K1*acc + K0) ----
    const int rbase = wm * 64 + (lane >> 2);
    const float K1 = 2.8853900817779268f;              // 2*log2(e)
    const float K0 = -2.8853900817779268f;

    float dR[8];
#pragma unroll
    for (int x = 0; x < 8; x++) dR[x] = 0.f;

    if (offdiag) {
#pragma unroll
        for (int nf = 0; nf < 4; nf++) {
#pragma unroll
            for (int e = 0; e < 2; e++) {
                const int cloc = wn * 32 + nf * 8 + 2 * (lane & 3) + e;
                float dc = 0.f;
#pragma unroll
                for (int mf = 0; mf < 4; mf++) {
#pragma unroll
                    for (int h = 0; h < 2; h++) {
                        const float ex = ex2f(fmaf(acc[mf][nf][h * 2 + e], K1, K0));
                        dR[mf * 2 + h] += ex;
                        dc += ex;
                    }
                }
                dc += __shfl_xor_sync(0xFFFFFFFF, dc, 4);
                dc += __shfl_xor_sync(0xFFFFFFFF, dc, 8);
                dc += __shfl_xor_sync(0xFFFFFFFF, dc, 16);
                if ((lane >> 2) == 0) atomicAdd(&redDc[cloc], dc);
            }
        }
    } else {
#pragma unroll
        for (int nf = 0; nf < 4; nf++) {
#pragma unroll
            for (int e = 0; e < 2; e++) {
                const int cloc = wn * 32 + nf * 8 + 2 * (lane & 3) + e;
#pragma unroll
                for (int mf = 0; mf < 4; mf++) {
#pragma unroll
                    for (int h = 0; h < 2; h++) {
                        const int rloc = rbase + mf * 16 + 8 * h;
                        const float ex = ex2f(fmaf(acc[mf][nf][h * 2 + e], K1, K0));
                        if (rloc != cloc) dR[mf * 2 + h] += ex;   // exclude self
                    }
                }
            }
        }
    }
#pragma unroll
    for (int x = 0; x < 8; x++) {
        float d = dR[x];
        d += __shfl_xor_sync(0xFFFFFFFF, d, 1);
        d += __shfl_xor_sync(0xFFFFFFFF, d, 2);
        if ((lane & 3) == 0) {
            const int rloc = rbase + (x >> 1) * 16 + 8 * (x & 1);
            atomicAdd(&redD[rloc], d);
        }
    }

    __syncthreads();
    if (tid < BM) {
        atomicAdd(&g_denom[row0 + tid], redD[tid]);
        if (offdiag) atomicAdd(&g_denom[col0 + tid], redDc[tid]);
    }
}

// ---- parallel reduce: 32 blocks, warp-shfl reduction, 1 sync ----
__global__ void reduce_kernel(const int* __restrict__ Lraw) {
    __shared__ double wred[8];
    const int tid = threadIdx.x;
    const int i = blockIdx.x * 256 + tid;              // row id, 0..8191
    const int is64 = g_is64;
    const float LN2 = 0.6931471805599453f;

    const int P = g_cnt[get_label(Lraw, i, is64)] - 1;
    const float lg = lg2f(g_denom[i]) * LN2;           // log(denom)
    double v = (double)P * (2.0 + (double)lg);

    const float c0 = g_C[2 * i];                       // 16384 C elems, 2/thread
    const float c1 = g_C[2 * i + 1];
    v -= 2.0 * ((double)c0 * c0 + (double)c1 * c1);

#pragma unroll
    for (int s = 16; s > 0; s >>= 1) v += __shfl_xor_sync(0xFFFFFFFF, v, s);
    if ((tid & 31) == 0) wred[tid >> 5] = v;
    __syncthreads();
    if (tid < 8) {
        double w = wred[tid];
        w += __shfl_xor_sync(0xFF, w, 1);
        w += __shfl_xor_sync(0xFF, w, 2);
        w += __shfl_xor_sync(0xFF, w, 4);
        if (tid == 0) atomicAdd(&g_acc, w);
    }
}

// ---- final: npos + scalar write ----
__global__ void final_kernel(float* __restrict__ out) {
    __shared__ long long s_np[NCLS];
    const int tid = threadIdx.x;                       // 64 threads
    long long c = g_cnt[tid];
    s_np[tid] = c * (c - 1);
    __syncthreads();
    if (tid == 0) {
        long long npos = 0;
        for (int k = 0; k < NCLS; k++) npos += s_np[k];
        out[0] = (float)((g_acc + 2.0 * (double)N_ROWS) / (double)npos);
    }
}

extern "C" void kernel_launch(void* const* d_in, const int* in_sizes, int n_in,
                              void* d_out, int out_size) {
    const float* E    = (const float*)d_in[0];
    const int*   Lraw = (const int*)d_in[1];   // width auto-detected on device
    float* out = (float*)d_out;

    const int DYN_SMEM = 2 * BM * SROWB;       // A+B tiles, full K: 69632 B
    cudaFuncSetAttribute(sim_kernel, cudaFuncAttributeMaxDynamicSharedMemorySize, DYN_SMEM);

    prep_kernel<<<(N_ROWS * DIM / 16) / 256, 256>>>(E, Lraw);
    csum_kernel<<<DIM / 4, 256>>>(E, Lraw);
    sim_kernel<<<NTILES, NTHR, DYN_SMEM>>>();
    reduce_kernel<<<N_ROWS / 256, 256>>>(Lraw);
    final_kernel<<<1, NCLS>>>(out);
}